// round 5
// baseline (speedup 1.0000x reference)
#include <cuda_runtime.h>

#define FULLMASK 0xffffffffu
#define NTAGS 32
#define BOS_IDX 30
#define EOS_IDX 31
#define L2E 1.4426950408889634f
#define LN2 0.6931471805599453f

typedef unsigned long long ull;

static __device__ __forceinline__ void ffma2(ull& d, ull a, ull b) {
    asm("fma.rn.f32x2 %0, %1, %2, %0;" : "+l"(d) : "l"(a), "l"(b));
}
static __device__ __forceinline__ ull add2(ull a, ull b) {
    ull r;
    asm("add.rn.f32x2 %0, %1, %2;" : "=l"(r) : "l"(a), "l"(b));
    return r;
}
static __device__ __forceinline__ float ex2_(float x) {
    float r; asm("ex2.approx.f32 %0, %1;" : "=f"(r) : "f"(x)); return r;
}
static __device__ __forceinline__ float lg2_(float x) {
    float r; asm("lg2.approx.f32 %0, %1;" : "=f"(r) : "f"(x)); return r;
}

// s_j = sum_i G[j,i]*beta_i for one sequence; betas read as 64-bit pairs.
static __device__ __forceinline__ float matvec32(const ull* er, unsigned base) {
    ull A = 0ull, B = 0ull, C = 0ull, D = 0ull;
    #pragma unroll
    for (int q = 0; q < 4; q++) {
        ull p0, p1, p2, p3;
        asm volatile("ld.shared.v2.u64 {%0,%1}, [%2];"
                     : "=l"(p0), "=l"(p1) : "r"(base + q * 32));
        asm volatile("ld.shared.v2.u64 {%0,%1}, [%2];"
                     : "=l"(p2), "=l"(p3) : "r"(base + q * 32 + 16));
        ffma2(A, er[4 * q + 0], p0);
        ffma2(B, er[4 * q + 1], p1);
        ffma2(C, er[4 * q + 2], p2);
        ffma2(D, er[4 * q + 3], p3);
    }
    ull S = add2(add2(A, B), add2(C, D));
    float x, y;
    asm("mov.b64 {%0,%1}, %2;" : "=f"(x), "=f"(y) : "l"(S));
    return x + y;
}

// One warp handles TWO sequences (independent chains interleaved by the
// scheduler), lane = tag. Multiplicative lag-1 recurrence per sequence:
//   s_j = sum_i G[j,i]*beta_i;  beta' = s * K;  K = ex2(em*L2E - D)
//   D = lg2(s_EOS of previous step) (off-chain, one step of slack); Csum += D.
// No __syncwarp: lanes are convergent and the per-warp LSU is in-order, so
// the step-t LDS cannot bypass the step-t STS.
__global__ __launch_bounds__(64, 1) void crf_forward_kernel(
    const float* __restrict__ emission,   // [B, T, 32]
    const float* __restrict__ trans,      // [32, 32]
    float* __restrict__ out,              // [B]
    int B, int T)
{
    const int lane = threadIdx.x & 31;
    const int w    = threadIdx.x >> 5;
    const int b0   = (blockIdx.x * 2 + w) * 2;   // first of this warp's 2 seqs

    __shared__ __align__(16) float sb[2][2][2][NTAGS]; // [warp][buf][seq][tag]

    if (b0 >= B) return;  // warp-uniform

    // one-time: G row for this lane (exp of transitions), packed f32x2
    ull er[16];
    {
        const float* trow = trans + lane * NTAGS;
        #pragma unroll
        for (int q = 0; q < 16; q++) {
            float x = expf(trow[2 * q]);     // exp(-1000) -> 0 for BOS row
            float y = expf(trow[2 * q + 1]);
            asm("mov.b64 %0, {%1,%2};" : "=l"(er[q]) : "f"(x), "f"(y));
        }
    }

    const float* em0 = emission + (size_t)b0 * T * NTAGS + lane;
    const float* em1 = em0 + (size_t)T * NTAGS;

    // step 0 analytic (only BOS survives init alpha), log2 units, EOS-anchored
    float tb = trans[lane * NTAGS + BOS_IDX];
    float a20 = (em0[0] + tb) * L2E;
    float a21 = (em1[0] + tb) * L2E;
    float Cs0 = __shfl_sync(FULLMASK, a20, EOS_IDX);
    float Cs1 = __shfl_sync(FULLMASK, a21, EOS_IDX);
    float beta0 = ex2_(a20 - Cs0);           // 0 on dead BOS lane
    float beta1 = ex2_(a21 - Cs1);
    float sE0 = 1.0f, sE1 = 1.0f;            // => D = 0 on first iteration

    // emission prefetch rings, depth 4 per sequence
    float r0[4], r1[4];
    #pragma unroll
    for (int i = 0; i < 4; i++) {
        int tt = (i + 1 < T) ? (i + 1) : (T - 1);
        r0[i] = em0[(size_t)tt * NTAGS];
        r1[i] = em1[(size_t)tt * NTAGS];
    }

    const unsigned sa = (unsigned)__cvta_generic_to_shared(&sb[w][0][0][0]);

    #pragma unroll 4
    for (int t = 1; t < T; ++t) {
        float e0 = r0[0], e1 = r1[0];
        r0[0] = r0[1]; r0[1] = r0[2]; r0[2] = r0[3];
        r1[0] = r1[1]; r1[1] = r1[2]; r1[2] = r1[3];
        int tp = (t + 4 < T) ? (t + 4) : (T - 1);
        r0[3] = em0[(size_t)tp * NTAGS];
        r1[3] = em1[(size_t)tp * NTAGS];

        // off-chain (lag-1): rescale constants from previous step's s_EOS
        float D0 = lg2_(sE0);
        float D1 = lg2_(sE1);
        Cs0 += D0;
        Cs1 += D1;
        float K0 = ex2_(fmaf(e0, L2E, -D0));
        float K1 = ex2_(fmaf(e1, L2E, -D1));

        unsigned base = sa + (t & 1) * (2 * NTAGS * 4);
        asm volatile("st.shared.f32 [%0], %1;"
                     :: "r"(base + lane * 4), "f"(beta0) : "memory");
        asm volatile("st.shared.f32 [%0], %1;"
                     :: "r"(base + NTAGS * 4 + lane * 4), "f"(beta1) : "memory");

        float s0 = matvec32(er, base);
        float s1 = matvec32(er, base + NTAGS * 4);

        sE0 = __shfl_sync(FULLMASK, s0, EOS_IDX);  // consumed next iter
        sE1 = __shfl_sync(FULLMASK, s1, EOS_IDX);
        beta0 = s0 * K0;                           // only on-chain math
        beta1 = s1 * K1;
    }

    // materialize alpha (log2 units) and terminal lse per sequence
    float te = trans[EOS_IDX * NTAGS + lane] * L2E;
    float ah0 = lg2_(beta0) + Cs0;                 // -inf on BOS lane: ok
    float ah1 = lg2_(beta1) + Cs1;
    #pragma unroll
    for (int s = 0; s < 2; s++) {
        float v = (s == 0 ? ah0 : ah1) + te;
        float mm = v;
        #pragma unroll
        for (int o = 16; o; o >>= 1)
            mm = fmaxf(mm, __shfl_xor_sync(FULLMASK, mm, o));
        float ex = ex2_(v - mm);
        #pragma unroll
        for (int o = 16; o; o >>= 1)
            ex += __shfl_xor_sync(FULLMASK, ex, o);
        if (lane == 0 && b0 + s < B)
            out[b0 + s] = (mm + lg2_(ex)) * LN2;
    }
}

extern "C" void kernel_launch(void* const* d_in, const int* in_sizes, int n_in,
                              void* d_out, int out_size)
{
    const float* em = (const float*)d_in[0];
    const float* tr = (const float*)d_in[1];
    long long em_elems = in_sizes[0];
    if (n_in >= 2 && in_sizes[0] == NTAGS * NTAGS && in_sizes[1] > NTAGS * NTAGS) {
        em = (const float*)d_in[1];
        tr = (const float*)d_in[0];
        em_elems = in_sizes[1];
    }

    int B = out_size;
    int T = (int)(em_elems / ((long long)B * NTAGS));

    // 64 threads = 2 warps/CTA, 2 sequences per warp -> 4 sequences per CTA
    int blocks = (B + 3) / 4;
    crf_forward_kernel<<<blocks, 64>>>(em, tr, (float*)d_out, B, T);
}